// round 9
// baseline (speedup 1.0000x reference)
#include <cuda_runtime.h>
#include <cuda_bf16.h>
#include <cstddef>

// hungarian_matcher cost kernel
// out[b, q, j] = 5 * sum_d |pred_boxes[b,q,d] - target_boxes[b*64+j, d]|
//              - softmax(pred_logits[b,q,:])[target_ids[b*64+j]]
//
// R8 (resubmit after infra failure) = R2/R6 instruction stream (proven
// best: QPT=5, coalesced float4 target staging, stride-11 conflict-free
// LDS, broadcast pred LDS, coalesced scalar STG) with occupancy raised:
// block (64,5)=320 threads, QT=25 queries/CTA (900=36*25), grid
// (36,16)=576 CTAs -> 184k threads, ~1600-1920 resident threads/SM vs
// R2's ~1280.

namespace {

constexpr int BOX = 11;
constexpr int NC  = 4;
constexpr int PER = 64;
constexpr int QY  = 5;            // query groups per CTA
constexpr int QPT = 5;            // queries per thread
constexpr int QT  = QY * QPT;     // 25 queries per CTA
constexpr int NT  = PER * QY;     // 320 threads

__global__ __launch_bounds__(NT)
void matcher_kernel(const float* __restrict__ logits,
                    const float* __restrict__ boxes,
                    const float* __restrict__ tboxes,
                    const int*   __restrict__ tids,
                    float* __restrict__ out,
                    int nq)
{
    const int b  = blockIdx.y;
    const int q0 = blockIdx.x * QT;
    const int j  = threadIdx.x;           // target 0..63
    const int qy = threadIdx.y;           // 0..4
    const int t  = qy * PER + j;          // linear tid 0..319

    __shared__ float s_tb[PER * BOX];          // 704 floats, stride-11 rows
    __shared__ float s_pb[QT * BOX];           // 275 floats
    __shared__ float s_negprob[QT * NC];       // 100 floats

    // --- Target boxes: coalesced float4 staging (176 lanes, one shot) ---
    {
        const float4* src = (const float4*)(tboxes + (size_t)b * PER * BOX);
        if (t < PER * BOX / 4) ((float4*)s_tb)[t] = src[t];
    }

    // --- Pred boxes for this tile: 275 floats, coalesced ---
    if (t < QT * BOX) {
        s_pb[t] = boxes[((size_t)b * nq + q0) * BOX + t];
    }

    // --- Softmax rows: thread t < QT handles query q0+t ---
    if (t < QT) {
        const float* lp = logits + ((size_t)b * nq + q0 + t) * NC;
        float l[NC];
        float m = -1e30f;
#pragma unroll
        for (int c = 0; c < NC; c++) { l[c] = lp[c]; m = fmaxf(m, l[c]); }
        float s = 0.0f;
#pragma unroll
        for (int c = 0; c < NC; c++) { l[c] = __expf(l[c] - m); s += l[c]; }
        const float inv = __frcp_rn(s);
#pragma unroll
        for (int c = 0; c < NC; c++) s_negprob[t * NC + c] = -l[c] * inv;
    }

    // Class id (coalesced 4B LDG across j, L1-resident)
    const int cls = tids[b * PER + j];

    __syncthreads();

    // --- Target box -> registers: 11 LDS, stride 11, conflict-free ---
    float tb[BOX];
#pragma unroll
    for (int d = 0; d < BOX; d++) tb[d] = s_tb[j * BOX + d];

    // --- 5 query rows; pred-box LDS are warp-uniform broadcasts ---
    float* orow = out + ((size_t)b * nq + q0 + qy * QPT) * PER + j;
#pragma unroll
    for (int k = 0; k < QPT; k++) {
        const int ql = qy * QPT + k;
        float sa = 0.0f, sb = 0.0f;
#pragma unroll
        for (int d = 0; d < BOX; d += 2) {
            sa += fabsf(s_pb[ql * BOX + d] - tb[d]);
            if (d + 1 < BOX) sb += fabsf(s_pb[ql * BOX + d + 1] - tb[d + 1]);
        }
        orow[(size_t)k * PER] = fmaf(5.0f, sa + sb, s_negprob[ql * NC + cls]);
    }
}

} // namespace

extern "C" void kernel_launch(void* const* d_in, const int* in_sizes, int n_in,
                              void* d_out, int out_size)
{
    const float* logits = (const float*)d_in[0];
    const float* boxes  = (const float*)d_in[1];
    const float* tboxes = (const float*)d_in[2];
    const int*   tids   = (const int*)d_in[3];
    float* out = (float*)d_out;

    const int n_total = in_sizes[3];                 // 1024
    const int box_dim = in_sizes[2] / n_total;       // 11
    const int bsnq    = in_sizes[1] / box_dim;       // 14400
    const int per     = out_size / bsnq;             // 64
    const int bs      = n_total / per;               // 16
    const int nq      = bsnq / bs;                   // 900

    (void)n_in; (void)box_dim; (void)per;

    dim3 block(PER, QY);
    dim3 grid(nq / QT, bs);                          // (36, 16) = 576
    matcher_kernel<<<grid, block>>>(logits, boxes, tboxes, tids, out, nq);
}

// round 10
// speedup vs baseline: 1.0199x; 1.0199x over previous
#include <cuda_runtime.h>
#include <cuda_bf16.h>
#include <cstddef>

// hungarian_matcher cost kernel
// out[b, q, j] = 5 * sum_d |pred_boxes[b,q,d] - target_boxes[b*64+j, d]|
//              - softmax(pred_logits[b,q,:])[target_ids[b*64+j]]
//
// R10 = R2/R6 shape (block (64,4)=256, QT=20, QPT=5, grid (45,16)=720,
// best measured: 6.72us, occ 51%, issue 40%) with the smem read path
// vectorized: both tiles padded to 12-float rows so the per-thread target
// box is 3 LDS.128 (stride-48B: 8-lane phases partition all 32 banks ->
// conflict-free) and each pred row is 3 broadcast LDS.128 instead of 11
// scalar LDS. ~22% fewer issued instructions at unchanged occupancy.

namespace {

constexpr int BOX  = 11;
constexpr int BOXP = 12;          // padded row, 48B (float4-aligned)
constexpr int NC   = 4;
constexpr int PER  = 64;
constexpr int QT   = 20;          // queries per CTA (900 = 45*20)
constexpr int QPT  = 5;           // queries per thread
constexpr int NT   = PER * 4;     // 256 threads

__global__ __launch_bounds__(NT)
void matcher_kernel(const float* __restrict__ logits,
                    const float* __restrict__ boxes,
                    const float* __restrict__ tboxes,
                    const int*   __restrict__ tids,
                    float* __restrict__ out,
                    int nq)
{
    const int b  = blockIdx.y;
    const int q0 = blockIdx.x * QT;
    const int j  = threadIdx.x;           // target 0..63
    const int qy = threadIdx.y;           // 0..3
    const int t  = qy * PER + j;          // linear tid

    __shared__ float s_tb[PER * BOXP];         // 768 floats, 12-padded rows
    __shared__ float s_pb[QT * BOXP];          // 240 floats, 12-padded rows
    __shared__ float s_negprob[QT * NC];       // 80 floats

    // --- Target boxes: coalesced LDG, padded STS (704 elems, 3 rounds) ---
    for (int i = t; i < PER * BOX; i += NT) {
        const int row = i / BOX, col = i - row * BOX;
        s_tb[row * BOXP + col] = tboxes[(size_t)b * PER * BOX + i];
    }

    // --- Pred boxes for this tile: 220 elems, coalesced LDG, padded STS ---
    if (t < QT * BOX) {
        const int row = t / BOX, col = t - row * BOX;
        s_pb[row * BOXP + col] = boxes[((size_t)b * nq + q0) * BOX + t];
    }

    // --- Softmax rows: thread t < QT handles query q0+t ---
    if (t < QT) {
        const float* lp = logits + ((size_t)b * nq + q0 + t) * NC;
        float l[NC];
        float m = -1e30f;
#pragma unroll
        for (int c = 0; c < NC; c++) { l[c] = lp[c]; m = fmaxf(m, l[c]); }
        float s = 0.0f;
#pragma unroll
        for (int c = 0; c < NC; c++) { l[c] = __expf(l[c] - m); s += l[c]; }
        const float inv = __frcp_rn(s);
#pragma unroll
        for (int c = 0; c < NC; c++) s_negprob[t * NC + c] = -l[c] * inv;
    }

    // Class id (coalesced 4B LDG across j, L1-resident)
    const int cls = tids[b * PER + j];

    __syncthreads();

    // --- Target box -> registers: 3 LDS.128, conflict-free ---
    float tb[BOXP];
    {
        const float4* tr = (const float4*)(s_tb + j * BOXP);
#pragma unroll
        for (int v = 0; v < 3; v++) ((float4*)tb)[v] = tr[v];
    }

    // --- 5 query rows; pred rows via 3 broadcast LDS.128 each ---
    float* orow = out + ((size_t)b * nq + q0 + qy * QPT) * PER + j;
#pragma unroll
    for (int k = 0; k < QPT; k++) {
        const int ql = qy * QPT + k;

        float pbf[BOXP];
        {
            const float4* pr = (const float4*)(s_pb + ql * BOXP);
#pragma unroll
            for (int v = 0; v < 3; v++) ((float4*)pbf)[v] = pr[v];
        }

        float sa = 0.0f, sb = 0.0f;
#pragma unroll
        for (int d = 0; d < BOX; d += 2) {
            sa += fabsf(pbf[d] - tb[d]);
            if (d + 1 < BOX) sb += fabsf(pbf[d + 1] - tb[d + 1]);
        }
        orow[(size_t)k * PER] = fmaf(5.0f, sa + sb, s_negprob[ql * NC + cls]);
    }
}

} // namespace

extern "C" void kernel_launch(void* const* d_in, const int* in_sizes, int n_in,
                              void* d_out, int out_size)
{
    const float* logits = (const float*)d_in[0];
    const float* boxes  = (const float*)d_in[1];
    const float* tboxes = (const float*)d_in[2];
    const int*   tids   = (const int*)d_in[3];
    float* out = (float*)d_out;

    const int n_total = in_sizes[3];                 // 1024
    const int box_dim = in_sizes[2] / n_total;       // 11
    const int bsnq    = in_sizes[1] / box_dim;       // 14400
    const int per     = out_size / bsnq;             // 64
    const int bs      = n_total / per;               // 16
    const int nq      = bsnq / bs;                   // 900

    (void)n_in; (void)box_dim; (void)per;

    dim3 block(PER, 4);
    dim3 grid(nq / QT, bs);                          // (45, 16) = 720
    matcher_kernel<<<grid, block>>>(logits, boxes, tboxes, tids, out, nq);
}